// round 16
// baseline (speedup 1.0000x reference)
#include <cuda_runtime.h>
#include <math.h>

#define BB 16
#define NN 1536
#define FF 128
#define NB 128
#define NCHK 48

// ---------------- scratch (device globals; no allocation) ----------------
__device__ __align__(16) float g_h0[NN * FF];
__device__ float g_si0[NN];
__device__ float g_sj0[NN];
__device__ int   g_idx[BB][NN];
__device__ int   g_n[BB];
__device__ __align__(16) float g_hc[(size_t)BB * NN * FF];   // layer-0 h compacted
__device__ __align__(16) float g_xc[(size_t)BB * NN * FF];   // layer-1 h
__device__ __align__(16) float g_mean[(size_t)BB * NN * FF]; // combine outputs (x1, then x2)
__device__ float g_sic[BB * NN];
__device__ float g_sjc[BB * NN];
__device__ float g_kldrow1[BB * NN];
__device__ float g_kldrow2[BB * NN];
__device__ __align__(16) float g_hlast[FF];
__device__ float g_sL[2];
__device__ float g_feat[BB * FF];
__device__ __align__(16) float g_Wcomb[FF * FF];
__device__ __align__(16) float g_bcomb[FF];
__device__ __align__(16) float g_udst[FF];   // u = pW_mean @ (dec_W @ a_dst)
__device__ float g_cdst;                     // cb = pb_mean . (dec_W @ a_dst)

// bucket-factorized attention scratch
__device__ int   g_ord[BB][NN];
__device__ float g_sjo[BB][NN];
__device__ float g_vso[BB][NN];
__device__ float g_bso[BB][NN];
__device__ int   g_bstart[BB][NB + 4];
__device__ __align__(16) float g_Cv[BB][(NB + 1) * FF];
__device__ __align__(16) float g_Cb[BB][(NB + 1) * FF];
__device__ float g_CvS[BB][NB + 1];
__device__ float g_CbS[BB][NB + 1];
__device__ float g_bmax[BB];
__device__ float g_bscale[BB];

// ============ launch-1 kernel: layer-0 GEMM + side tasks ============
// blocks 0-47: embed@encW0 -> g_h0 + si0/sj0
// blk 48: hlast + bcomb + u/cb; blks 49-52: Wcomb; blks 53-68: compaction
__global__ void gemm0(const float* __restrict__ Aext,
                      const float* __restrict__ W,
                      const float* __restrict__ asrc, const float* __restrict__ adst,
                      const float* __restrict__ hW, const float* __restrict__ hs2,
                      const float* __restrict__ hd2,
                      const float* __restrict__ pWm, const float* __restrict__ pbm,
                      const int* __restrict__ dataPtr)
{
    int t = threadIdx.x;  // 128
    if (blockIdx.x >= 53) {
        int b = blockIdx.x - 53;
        if (t < 32) {
            const int* d = dataPtr + b * NN;
            int cnt = 0;
            for (int base = 0; base < NN; base += 32) {
                int v = d[base + t];
                unsigned m = __ballot_sync(0xffffffffu, v != 0);
                if (v != 0) g_idx[b][cnt + __popc(m & ((1u << t) - 1u))] = base + t;
                cnt += __popc(m);
            }
            if (t == 0) g_n[b] = cnt;
        }
        return;
    }
    if (blockIdx.x == 48) {
        __shared__ float sh[128];
        __shared__ float sh2[4];
        const float* e = Aext + (size_t)NN * FF;
        float acc = 0.f;
        #pragma unroll 8
        for (int k = 0; k < FF; k++) acc += e[k] * hW[k * FF + t];
        g_hlast[t] = acc;
        sh[t] = acc * hs2[t];
        __syncthreads();
        for (int s = 64; s > 0; s >>= 1) { if (t < s) sh[t] += sh[t + s]; __syncthreads(); }
        if (t == 0) g_sL[0] = sh[0];
        __syncthreads();
        sh[t] = acc * hd2[t];
        __syncthreads();
        for (int s = 64; s > 0; s >>= 1) { if (t < s) sh[t] += sh[t + s]; __syncthreads(); }
        if (t == 0) g_sL[1] = sh[0];
        float bc = 0.f;
        #pragma unroll 8
        for (int m = 0; m < FF; m++) bc += pbm[m] * hW[m * FF + t];
        g_bcomb[t] = bc;
        // v = dec_W @ a_dst  (per row m), then u = pW_mean @ v, cb = pb . v
        __syncthreads();
        float v = 0.f;
        #pragma unroll 8
        for (int c = 0; c < FF; c++) v += hW[t * FF + c] * hd2[c];
        sh[t] = v;
        __syncthreads();
        float cbp = pbm[t] * sh[t];
        #pragma unroll
        for (int o = 16; o > 0; o >>= 1) cbp += __shfl_xor_sync(0xffffffffu, cbp, o);
        if ((t & 31) == 0) sh2[t >> 5] = cbp;
        float uu = 0.f;
        #pragma unroll 8
        for (int m = 0; m < FF; m++) uu += pWm[(size_t)t * 2 * FF + m] * sh[m];
        g_udst[t] = uu;
        __syncthreads();
        if (t == 0) g_cdst = sh2[0] + sh2[1] + sh2[2] + sh2[3];
        return;
    }

    bool wcomb = (blockIdx.x >= 49);
    int n = wcomb ? FF : NN;
    int i0 = wcomb ? (blockIdx.x - 49) * 32 : blockIdx.x * 32;

    const float* A   = wcomb ? pWm : Aext;
    int lda          = wcomb ? 2 * FF : FF;
    const float* Wp  = wcomb ? hW : W;
    float* C         = wcomb ? g_Wcomb : g_h0;

    __shared__ float shA[16][36];
    __shared__ __align__(16) float shW[16][128];

    int ty = t >> 4, tx = t & 15;
    int rowA = t >> 2, c4A = t & 3;
    const float* Arow = A + (size_t)(i0 + rowA) * lda + c4A * 4;
    float acc[4][8] = {};
    float4 pA, pW4[4];

    pA = *(const float4*)(Arow);
    #pragma unroll
    for (int p = 0; p < 4; p++) {
        int u = t + 128 * p;
        pW4[p] = *(const float4*)&Wp[(size_t)(u >> 5) * FF + (u & 31) * 4];
    }

    for (int k0 = 0; k0 < FF; k0 += 16) {
        __syncthreads();
        shA[c4A * 4 + 0][rowA] = pA.x;
        shA[c4A * 4 + 1][rowA] = pA.y;
        shA[c4A * 4 + 2][rowA] = pA.z;
        shA[c4A * 4 + 3][rowA] = pA.w;
        #pragma unroll
        for (int p = 0; p < 4; p++) {
            int u = t + 128 * p;
            *(float4*)&shW[u >> 5][(u & 31) * 4] = pW4[p];
        }
        __syncthreads();

        if (k0 + 16 < FF) {
            pA = *(const float4*)(Arow + k0 + 16);
            #pragma unroll
            for (int p = 0; p < 4; p++) {
                int u = t + 128 * p;
                pW4[p] = *(const float4*)&Wp[(size_t)(k0 + 16 + (u >> 5)) * FF + (u & 31) * 4];
            }
        }

        #pragma unroll
        for (int k = 0; k < 16; k++) {
            float av[4], bv[8];
            *(float4*)&av[0] = *(float4*)&shA[k][ty * 4];
            *(float4*)&bv[0] = *(float4*)&shW[k][tx * 8];
            *(float4*)&bv[4] = *(float4*)&shW[k][tx * 8 + 4];
            #pragma unroll
            for (int r = 0; r < 4; r++)
                #pragma unroll
                for (int c = 0; c < 8; c++)
                    acc[r][c] = fmaf(av[r], bv[c], acc[r][c]);
        }
    }

    if (wcomb) {
        #pragma unroll
        for (int r = 0; r < 4; r++) {
            int i = i0 + ty * 4 + r;
            *(float4*)&C[(size_t)i * FF + tx * 8]     = make_float4(acc[r][0], acc[r][1], acc[r][2], acc[r][3]);
            *(float4*)&C[(size_t)i * FF + tx * 8 + 4] = make_float4(acc[r][4], acc[r][5], acc[r][6], acc[r][7]);
        }
        return;
    }

    float as8[8], ad8[8];
    #pragma unroll
    for (int c = 0; c < 8; c++) { as8[c] = asrc[tx * 8 + c]; ad8[c] = adst[tx * 8 + c]; }
    float ss[4], sd[4];
    #pragma unroll
    for (int r = 0; r < 4; r++) {
        int i = i0 + ty * 4 + r;
        float s1 = 0.f, s2 = 0.f;
        #pragma unroll
        for (int c = 0; c < 8; c++) { s1 += acc[r][c] * as8[c]; s2 += acc[r][c] * ad8[c]; }
        ss[r] = s1; sd[r] = s2;
        *(float4*)&C[(size_t)i * FF + tx * 8]     = make_float4(acc[r][0], acc[r][1], acc[r][2], acc[r][3]);
        *(float4*)&C[(size_t)i * FF + tx * 8 + 4] = make_float4(acc[r][4], acc[r][5], acc[r][6], acc[r][7]);
    }
    #pragma unroll
    for (int r = 0; r < 4; r++) {
        #pragma unroll
        for (int o = 8; o > 0; o >>= 1) {
            ss[r] += __shfl_xor_sync(0xffffffffu, ss[r], o);
            sd[r] += __shfl_xor_sync(0xffffffffu, sd[r], o);
        }
    }
    if (tx == 0) {
        #pragma unroll
        for (int r = 0; r < 4; r++) {
            int i = i0 + ty * 4 + r;
            g_si0[i] = ss[r]; g_sj0[i] = sd[r];
        }
    }
}

// ============ column-split GEMM: 32x64 tile, 128 threads, 4x4/thread ============
// stage 0: L1 linear  (g_mean @ encW1 -> g_xc, si/sj via 2-way atomic)
// stage 1: z=0 mean-KLD, z=1 sigma-KLD (atomic kldrow)
__global__ void gemmC(int stage,
                      const float* __restrict__ encW1,
                      const float* __restrict__ eas1, const float* __restrict__ ead1,
                      const float* __restrict__ pW, const float* __restrict__ pb)
{
    int b = blockIdx.y;
    int n = g_n[b];
    int i0 = (blockIdx.x >> 1) * 32;
    if (i0 >= n) return;
    int c0 = (blockIdx.x & 1) * 64;
    int z = blockIdx.z;
    int t = threadIdx.x;  // 128

    const float* A = g_mean + (size_t)b * NN * FF;
    const float* Wp; const float* bp = nullptr; int ldw;
    float* C = nullptr;
    float* kldOut = nullptr; int kldExp = 0;
    int epi;  // 1 = store + si/sj, 2 = kld only

    if (stage == 0) {
        Wp = encW1 + c0; ldw = FF; C = g_xc + (size_t)b * NN * FF;
        epi = 1;
    } else if (z == 0) {
        Wp = pW + c0; ldw = 2 * FF; bp = pb + c0;
        kldOut = g_kldrow1 + b * NN; kldExp = 0; epi = 2;
    } else {
        Wp = pW + FF + c0; ldw = 2 * FF; bp = pb + FF + c0;
        kldOut = g_kldrow2 + b * NN; kldExp = 1; epi = 2;
    }

    __shared__ float shA[16][36];
    __shared__ __align__(16) float shW[16][64];

    int ty = t >> 4, tx = t & 15;
    int rowA = t >> 2, c4A = t & 3;
    bool rowAok = (i0 + rowA < n);
    const float* Arow = A + (size_t)(i0 + (rowAok ? rowA : 0)) * FF + c4A * 4;
    float acc[4][4] = {};
    float4 pA, pW2[2];

    pA = rowAok ? *(const float4*)(Arow) : make_float4(0.f, 0.f, 0.f, 0.f);
    #pragma unroll
    for (int p = 0; p < 2; p++) {
        int u = t + 128 * p;
        pW2[p] = *(const float4*)&Wp[(size_t)(u >> 4) * ldw + (u & 15) * 4];
    }

    for (int k0 = 0; k0 < FF; k0 += 16) {
        __syncthreads();
        shA[c4A * 4 + 0][rowA] = pA.x;
        shA[c4A * 4 + 1][rowA] = pA.y;
        shA[c4A * 4 + 2][rowA] = pA.z;
        shA[c4A * 4 + 3][rowA] = pA.w;
        #pragma unroll
        for (int p = 0; p < 2; p++) {
            int u = t + 128 * p;
            *(float4*)&shW[u >> 4][(u & 15) * 4] = pW2[p];
        }
        __syncthreads();

        if (k0 + 16 < FF) {
            pA = rowAok ? *(const float4*)(Arow + k0 + 16) : make_float4(0.f, 0.f, 0.f, 0.f);
            #pragma unroll
            for (int p = 0; p < 2; p++) {
                int u = t + 128 * p;
                pW2[p] = *(const float4*)&Wp[(size_t)(k0 + 16 + (u >> 4)) * ldw + (u & 15) * 4];
            }
        }

        #pragma unroll
        for (int k = 0; k < 16; k++) {
            float av[4], bv[4];
            *(float4*)&av[0] = *(float4*)&shA[k][ty * 4];
            *(float4*)&bv[0] = *(float4*)&shW[k][tx * 4];
            #pragma unroll
            for (int r = 0; r < 4; r++)
                #pragma unroll
                for (int c = 0; c < 4; c++)
                    acc[r][c] = fmaf(av[r], bv[c], acc[r][c]);
        }
    }

    if (epi == 2) {
        float bv4[4];
        #pragma unroll
        for (int c = 0; c < 4; c++) bv4[c] = bp[tx * 4 + c];
        #pragma unroll
        for (int r = 0; r < 4; r++) {
            int i = i0 + ty * 4 + r;
            float kp = 0.f;
            #pragma unroll
            for (int c = 0; c < 4; c++) {
                float v = acc[r][c] + bv4[c];
                kp += (kldExp == 0) ? v * v : (expm1f(v) - v);
            }
            #pragma unroll
            for (int o = 8; o > 0; o >>= 1) kp += __shfl_xor_sync(0xffffffffu, kp, o);
            if (tx == 0 && i < n) atomicAdd(&kldOut[i], kp);
        }
        return;
    }

    float as4[4], ad4[4];
    #pragma unroll
    for (int c = 0; c < 4; c++) {
        int idx = c0 + tx * 4 + c;
        as4[c] = eas1[idx]; ad4[c] = ead1[idx];
    }
    float ss[4], sd[4];
    #pragma unroll
    for (int r = 0; r < 4; r++) {
        int i = i0 + ty * 4 + r;
        float s1 = 0.f, s2 = 0.f;
        #pragma unroll
        for (int c = 0; c < 4; c++) {
            float v = acc[r][c];
            s1 += v * as4[c]; s2 += v * ad4[c];
        }
        ss[r] = s1; sd[r] = s2;
        if (i < n)
            *(float4*)&C[(size_t)i * FF + c0 + tx * 4] = make_float4(acc[r][0], acc[r][1], acc[r][2], acc[r][3]);
    }
    #pragma unroll
    for (int r = 0; r < 4; r++) {
        #pragma unroll
        for (int o = 8; o > 0; o >>= 1) {
            ss[r] += __shfl_xor_sync(0xffffffffu, ss[r], o);
            sd[r] += __shfl_xor_sync(0xffffffffu, sd[r], o);
        }
    }
    if (tx == 0) {
        #pragma unroll
        for (int r = 0; r < 4; r++) {
            int i = i0 + ty * 4 + r;
            if (i < n) { atomicAdd(&g_sic[b * NN + i], ss[r]); atomicAdd(&g_sjc[b * NN + i], sd[r]); }
        }
    }
}

// ============ attention prep ============
#define SQ_SJV  0
#define SQ_QV   (SQ_SJV + 1536)
#define SQ_RNK  (SQ_QV + 1536)
#define SQ_ORD  (SQ_RNK + 1536)
#define SQ_CNT  (SQ_ORD + 1536)
#define SQ_TOT  (SQ_CNT + NCHK * NB)
#define SQ_BST  (SQ_TOT + 128)
#define SQ_SJO  (SQ_BST + 132)
#define SQ_VSO  (SQ_SJO + 1536)
#define SQ_BSO  (SQ_VSO + 1536)
#define SQ_SV   (SQ_BSO + 1536)
#define SQ_SB   (SQ_SV + NB * 128)
#define SQ_SVS  (SQ_SB + NB * 128)
#define SQ_SBS  (SQ_SVS + 132)
#define SQ_RED  (SQ_SBS + 132)
#define SQ_TOTF (SQ_RED + 80)

__global__ void attn_prep(int hId)
{
    extern __shared__ float sm[];
    float* sjv = sm + SQ_SJV;
    int*   qv  = (int*)(sm + SQ_QV);
    int*   rnk = (int*)(sm + SQ_RNK);
    int*   ord = (int*)(sm + SQ_ORD);
    int*   cnt = (int*)(sm + SQ_CNT);
    int*   tot = (int*)(sm + SQ_TOT);
    int*   bst = (int*)(sm + SQ_BST);
    float* sjo = sm + SQ_SJO;
    float* vso = sm + SQ_VSO;
    float* bso = sm + SQ_BSO;
    float* Sv  = sm + SQ_SV;
    float* Sb  = sm + SQ_SB;
    float* SvS = sm + SQ_SVS;
    float* SbS = sm + SQ_SBS;
    float* red = sm + SQ_RED;

    int b = blockIdx.x;
    int n = g_n[b];
    int t = threadIdx.x;  // 1024
    int lane = t & 31, warp = t >> 5;
    const float* H = (hId ? g_xc : g_hc) + (size_t)b * NN * FF;

    if (hId == 0) {
        for (int u = t; u < n * 32; u += 1024)
            ((float4*)g_hc)[(size_t)b * NN * 32 + u] =
                ((const float4*)g_h0)[(size_t)g_idx[b][u >> 5] * 32 + (u & 31)];
        for (int jj = t; jj < n; jj += 1024) {
            int src = g_idx[b][jj];
            float sv = g_si0[src], dv = g_sj0[src];
            g_sic[b * NN + jj] = sv;
            g_sjc[b * NN + jj] = dv;
            sjv[jj] = dv;
        }
    } else {
        for (int u = t; u < n; u += 1024) sjv[u] = g_sjc[b * NN + u];
    }
    for (int u = t; u < NCHK * NB; u += 1024) cnt[u] = 0;
    __syncthreads();

    float mn = 1e30f, mx = -1e30f;
    for (int u = t; u < n; u += 1024) {
        float s = sjv[u];
        mn = fminf(mn, s); mx = fmaxf(mx, s);
    }
    #pragma unroll
    for (int o = 16; o > 0; o >>= 1) {
        mn = fminf(mn, __shfl_xor_sync(0xffffffffu, mn, o));
        mx = fmaxf(mx, __shfl_xor_sync(0xffffffffu, mx, o));
    }
    if (lane == 0) { red[warp] = mn; red[32 + warp] = mx; }
    __syncthreads();
    if (t == 0) {
        float a = 1e30f, z = -1e30f;
        for (int w = 0; w < 32; w++) { a = fminf(a, red[w]); z = fmaxf(z, red[32 + w]); }
        float span = z - a;
        float sc = (span > 1e-20f) ? (float)NB / span : 0.f;
        red[64] = z; red[65] = sc;
        g_bmax[b] = z; g_bscale[b] = sc;
    }
    __syncthreads();
    float bmax = red[64], bscale = red[65];

    int nchk = (n + 31) >> 5;
    for (int ch = warp; ch < nchk; ch += 32) {
        int j = ch * 32 + lane;
        int q = -1;
        if (j < n) {
            q = (int)((bmax - sjv[j]) * bscale);
            q = max(0, min(NB - 1, q));
        }
        unsigned mask = __match_any_sync(0xffffffffu, q);
        int rank = __popc(mask & ((1u << lane) - 1u));
        if (j < n) {
            qv[j] = q; rnk[j] = rank;
            if (rank == 0) cnt[ch * NB + q] = __popc(mask);
        }
    }
    __syncthreads();

    if (t < NB) {
        int run = 0;
        for (int ch = 0; ch < nchk; ch++) {
            int c = cnt[ch * NB + t];
            cnt[ch * NB + t] = run;
            run += c;
        }
        tot[t] = run;
    }
    __syncthreads();
    if (t < 32) {
        int base = t * 4;
        int h0 = tot[base], h1 = tot[base + 1], h2 = tot[base + 2], h3 = tot[base + 3];
        int s = h0 + h1 + h2 + h3, inc = s;
        #pragma unroll
        for (int o = 1; o < 32; o <<= 1) {
            int v = __shfl_up_sync(0xffffffffu, inc, o);
            if (lane >= o) inc += v;
        }
        int ex = inc - s;
        bst[base] = ex; bst[base + 1] = ex + h0;
        bst[base + 2] = ex + h0 + h1; bst[base + 3] = ex + h0 + h1 + h2;
        if (t == 31) bst[NB] = inc;
    }
    __syncthreads();
    if (t <= NB) g_bstart[b][t] = bst[t];

    for (int j = t; j < n; j += 1024) {
        int q = qv[j];
        int pos = bst[q] + cnt[(j >> 5) * NB + q] + rnk[j];
        ord[pos] = j;
    }
    __syncthreads();

    for (int pos = t; pos < n; pos += 1024) {
        int j = ord[pos];
        float s = sjv[j];
        float v = __expf(s), w = __expf(0.2f * s);
        sjo[pos] = s; vso[pos] = v; bso[pos] = w;
        g_ord[b][pos] = j; g_sjo[b][pos] = s; g_vso[b][pos] = v; g_bso[b][pos] = w;
    }
    __syncthreads();

    {
        int grp = t >> 7, c = t & 127;
        for (int q = grp; q < NB; q += 8) {
            int p0 = bst[q], p1 = bst[q + 1];
            float av = 0.f, ab = 0.f;
            for (int p = p0; p < p1; p++) {
                int jj = ord[p];
                float hv = H[(size_t)jj * FF + c];
                av = fmaf(vso[p], hv, av);
                ab = fmaf(bso[p], hv, ab);
            }
            Sv[q * 128 + c] = av;
            Sb[q * 128 + c] = ab;
            if (c == 0) { float s = 0.f; for (int p = p0; p < p1; p++) s += vso[p]; SvS[q] = s; }
            if (c == 1) { float s = 0.f; for (int p = p0; p < p1; p++) s += bso[p]; SbS[q] = s; }
        }
    }
    __syncthreads();

    if (t < 128) {
        float run = 0.f;
        for (int q = 0; q < NB; q++) { g_Cv[b][q * 128 + t] = run; run += Sv[q * 128 + t]; }
        g_Cv[b][NB * 128 + t] = run;
    } else if (t < 256) {
        int c = t - 128;
        float run = 0.f;
        for (int q = 0; q < NB; q++) { g_Cb[b][q * 128 + c] = run; run += Sb[q * 128 + c]; }
        g_Cb[b][NB * 128 + c] = run;
    } else if (t == 256) {
        float run = 0.f;
        for (int q = 0; q < NB; q++) { g_CvS[b][q] = run; run += SvS[q]; }
        g_CvS[b][NB] = run;
    } else if (t == 257) {
        float run = 0.f;
        for (int q = 0; q < NB; q++) { g_CbS[b][q] = run; run += SbS[q]; }
        g_CbS[b][NB] = run;
    }
}

// ============ per-row combine ============
__device__ __forceinline__ float4 combine_row(int b, int i, int lane, const float* __restrict__ H)
{
    float si = g_sic[b * NN + i];
    float uu = __expf(si), aa = __expf(0.2f * si);
    float th = -si;
    int qt = (int)((g_bmax[b] - th) * g_bscale[b]);
    qt = max(0, min(NB - 1, qt));
    int p0 = g_bstart[b][qt], p1 = g_bstart[b][qt + 1];

    float4 pv = *(const float4*)&g_Cv[b][qt * 128 + lane * 4];
    float4 pb = *(const float4*)&g_Cb[b][qt * 128 + lane * 4];
    float pvs = g_CvS[b][qt], pbs = g_CbS[b][qt];

    for (int p = p0; p < p1; p++) {
        float s = g_sjo[b][p];
        if (s >= th) {
            int jj = g_ord[b][p];
            float w = g_vso[b][p], wb = g_bso[b][p];
            float4 hv = *(const float4*)&H[(size_t)jj * FF + lane * 4];
            pv.x = fmaf(w, hv.x, pv.x); pv.y = fmaf(w, hv.y, pv.y);
            pv.z = fmaf(w, hv.z, pv.z); pv.w = fmaf(w, hv.w, pv.w);
            pb.x = fmaf(wb, hv.x, pb.x); pb.y = fmaf(wb, hv.y, pb.y);
            pb.z = fmaf(wb, hv.z, pb.z); pb.w = fmaf(wb, hv.w, pb.w);
            pvs += w; pbs += wb;
        }
    }

    float totbs = g_CbS[b][NB];
    float4 tb = *(const float4*)&g_Cb[b][NB * 128 + lane * 4];
    float inv = 1.f / (uu * pvs + aa * (totbs - pbs));
    float4 o;
    o.x = (uu * pv.x + aa * (tb.x - pb.x)) * inv;
    o.y = (uu * pv.y + aa * (tb.y - pb.y)) * inv;
    o.z = (uu * pv.z + aa * (tb.z - pb.z)) * inv;
    o.w = (uu * pv.w + aa * (tb.w - pb.w)) * inv;
    o.x = (o.x > 0.f) ? o.x : expm1f(o.x);
    o.y = (o.y > 0.f) ? o.y : expm1f(o.y);
    o.z = (o.z > 0.f) ? o.z : expm1f(o.z);
    o.w = (o.w > 0.f) ? o.w : expm1f(o.w);
    return o;
}

// ============ combine -> g_mean; zeroes accumulators for the next stage's atomics ============
__global__ void attn_combine(int hId)
{
    int b = blockIdx.y;
    int n = g_n[b];
    int warp = threadIdx.x >> 5, lane = threadIdx.x & 31;
    int i = blockIdx.x * 8 + warp;
    if (i >= n) return;
    const float* H = (hId ? g_xc : g_hc) + (size_t)b * NN * FF;
    float4 o = combine_row(b, i, lane, H);
    *(float4*)&g_mean[(size_t)b * NN * FF + (size_t)i * FF + lane * 4] = o;
    if (lane == 0) {
        if (hId == 0) { g_sic[b * NN + i] = 0.f; g_sjc[b * NN + i] = 0.f; }
        else          { g_kldrow1[b * NN + i] = 0.f; g_kldrow2[b * NN + i] = 0.f; }
    }
}

// ============ decoder: algebraic single-row attention over g_mean (x2) ============
__global__ void dec2_kernel()
{
    int b = blockIdx.x;
    int n = g_n[b];
    const float* M = g_mean + (size_t)b * NN * FF;
    int t = threadIdx.x;            // 1024
    int warp = t >> 5, lane = t & 31;
    __shared__ float smb[32 * 128];
    __shared__ float sS[32];
    __shared__ float sTot;

    float4 u4 = *(const float4*)&g_udst[lane * 4];
    float cb = g_cdst;
    float sLs = g_sL[0];

    float4 mb = make_float4(0.f, 0.f, 0.f, 0.f);
    float S = 0.f;
    for (int i = warp; i < n; i += 32) {
        float4 m = *(const float4*)&M[(size_t)i * FF + lane * 4];
        float d = m.x * u4.x + m.y * u4.y + m.z * u4.z + m.w * u4.w;
        #pragma unroll
        for (int o = 16; o > 0; o >>= 1) d += __shfl_xor_sync(0xffffffffu, d, o);
        float e = sLs + d + cb;
        e = (e >= 0.f) ? e : 0.2f * e;
        float w = __expf(e);
        S += w;
        mb.x = fmaf(w, m.x, mb.x); mb.y = fmaf(w, m.y, mb.y);
        mb.z = fmaf(w, m.z, mb.z); mb.w = fmaf(w, m.w, mb.w);
    }
    *(float4*)&smb[warp * 128 + lane * 4] = mb;
    if (lane == 0) sS[warp] = S;
    __syncthreads();
    float colsum = 0.f;
    if (t < 128) {
        #pragma unroll
        for (int w = 0; w < 32; w++) colsum += smb[w * 128 + t];
    }
    if (t == 128) {
        float s = 0.f;
        for (int w = 0; w < 32; w++) s += sS[w];
        sTot = s;
    }
    __syncthreads();
    if (t < 128) smb[t] = colsum;   // mbar
    __syncthreads();
    if (t < 128) {
        float acc = 0.f;
        #pragma unroll 8
        for (int k = 0; k < FF; k++) acc += smb[k] * g_Wcomb[k * FF + t];
        float eL = sLs + g_sL[1];
        eL = (eL >= 0.f) ? eL : 0.2f * eL;
        float wL = __expf(eL);
        float Stot = sTot;
        float val = (acc + Stot * g_bcomb[t] + wL * g_hlast[t]) / (Stot + wL);
        g_feat[b * FF + t] = fmaxf(val, 0.f);
    }
}

// ============ output MLP + KLD total ============
__global__ void final_kernel(const float* __restrict__ W1, const float* __restrict__ b1,
                             const float* __restrict__ W2, const float* __restrict__ b2,
                             float* __restrict__ out)
{
    int t = threadIdx.x; // 256
    __shared__ float shh[16 * 128];
    for (int u = t; u < 16 * 128; u += 256) {
        int b = u >> 7, c = u & 127;
        const float* f = g_feat + b * FF;
        float acc = b1[c];
        for (int k = 0; k < FF; k++) acc += f[k] * W1[k * FF + c];
        shh[u] = fmaxf(acc, 0.f);
    }
    __shared__ float shr[256];
    float kld = 0.f;
    for (int b = 0; b < BB; b++) {
        int n = g_n[b];
        float p = 0.f;
        for (int r = t; r < n; r += 256) p += g_kldrow1[b * NN + r] + g_kldrow2[b * NN + r];
        shr[t] = p;
        __syncthreads();
        for (int s = 128; s > 0; s >>= 1) { if (t < s) shr[t] += shr[t + s]; __syncthreads(); }
        if (t == 0) kld += 0.5f * shr[0] / fmaxf((float)n, 1.f);
        __syncthreads();
    }
    __syncthreads();
    if (t < 16) {
        float acc = b2[0];
        for (int c = 0; c < FF; c++) acc += shh[t * FF + c] * W2[c];
        out[t] = acc;
    }
    if (t == 0) out[16] = kld;
}

// ============ launch ============
extern "C" void kernel_launch(void* const* d_in, const int* in_sizes, int n_in,
                              void* d_out, int out_size)
{
    (void)in_sizes; (void)n_in; (void)out_size;
    const int*   data  = (const int*)d_in[0];
    const float* embed = (const float*)d_in[1];
    const float* encW  = (const float*)d_in[2];
    const float* eas   = (const float*)d_in[3];
    const float* ead   = (const float*)d_in[4];
    const float* pW    = (const float*)d_in[5];
    const float* pb    = (const float*)d_in[6];
    const float* dW    = (const float*)d_in[7];
    const float* das   = (const float*)d_in[8];
    const float* dad   = (const float*)d_in[9];
    const float* oW1   = (const float*)d_in[10];
    const float* ob1   = (const float*)d_in[11];
    const float* oW2   = (const float*)d_in[12];
    const float* ob2   = (const float*)d_in[13];
    float* out = (float*)d_out;

    const int SMEMB = SQ_TOTF * 4;
    cudaFuncSetAttribute(attn_prep, cudaFuncAttributeMaxDynamicSharedMemorySize, SMEMB);

    // 1) layer-0 h + si0/sj0 (+ hlast/bcomb/u/cb blk48, Wcomb 49-52, compaction 53-68)
    gemm0<<<dim3(69, 1), 128>>>(embed, encW, eas, ead, dW, das, dad, pW, pb, data);
    // 2) L1 attention prep
    attn_prep<<<16, 1024, SMEMB>>>(0);
    // 3) L1 combine -> g_mean (zeroes sic/sjc for stage-4 atomics)
    attn_combine<<<dim3(192, 16), 256>>>(0);
    // 4) L1 linear (col-split): x1 @ encW1 -> g_xc + atomic sic/sjc
    gemmC<<<dim3(96, 16), 128>>>(0, encW + FF * FF, eas + FF, ead + FF, pW, pb);
    // 5) L2 attention prep
    attn_prep<<<16, 1024, SMEMB>>>(1);
    // 6) L2 combine -> g_mean (zeroes kldrows for stage-7 atomics)
    attn_combine<<<dim3(192, 16), 256>>>(1);
    // 7) param head KLD only (z=0 mean, z=1 sigma), col-split
    gemmC<<<dim3(96, 16, 2), 128>>>(1, encW + FF * FF, eas + FF, ead + FF, pW, pb);
    // 8) decoder row (algebraic: no dec GEMM, no dec h matrix)
    dec2_kernel<<<16, 1024>>>();
    // 9) output MLP + KLD
    final_kernel<<<1, 256>>>(oW1, ob1, oW2, ob2, out);
}

// round 17
// speedup vs baseline: 1.1100x; 1.1100x over previous
#include <cuda_runtime.h>
#include <math.h>

#define BB 16
#define NN 1536
#define FF 128
#define NB 128
#define NCHK 48

// ---------------- scratch (device globals; no allocation) ----------------
__device__ __align__(16) float g_h0[NN * FF];
__device__ float g_si0[NN];
__device__ float g_sj0[NN];
__device__ int   g_idx[BB][NN];
__device__ int   g_n[BB];
__device__ __align__(16) float g_xc[(size_t)BB * NN * FF];   // layer-1 h
__device__ __align__(16) float g_mean[(size_t)BB * NN * FF]; // combine outputs (x1, then x2)
__device__ float g_sic[BB * NN];
__device__ float g_sjc[BB * NN];
__device__ float g_kldrow1[BB * NN];
__device__ float g_kldrow2[BB * NN];
__device__ __align__(16) float g_hlast[FF];
__device__ float g_sL[2];
__device__ float g_feat[BB * FF];
__device__ __align__(16) float g_Wcomb[FF * FF];
__device__ __align__(16) float g_bcomb[FF];
__device__ __align__(16) float g_udst[FF];   // u = pW_mean @ (dec_W @ a_dst)
__device__ float g_cdst;                     // cb = pb_mean . (dec_W @ a_dst)

// bucket-factorized attention scratch
__device__ int   g_ord[BB][NN];     // H-row indices in bucket order
__device__ float g_sjo[BB][NN];
__device__ float g_vso[BB][NN];
__device__ float g_bso[BB][NN];
__device__ int   g_bstart[BB][NB + 4];
__device__ __align__(16) float g_Cv[BB][(NB + 1) * FF];
__device__ __align__(16) float g_Cb[BB][(NB + 1) * FF];
__device__ float g_CvS[BB][NB + 1];
__device__ float g_CbS[BB][NB + 1];
__device__ float g_bmax[BB];
__device__ float g_bscale[BB];

// ============ launch-1 kernel: layer-0 GEMM + side tasks ============
__global__ void gemm0(const float* __restrict__ Aext,
                      const float* __restrict__ W,
                      const float* __restrict__ asrc, const float* __restrict__ adst,
                      const float* __restrict__ hW, const float* __restrict__ hs2,
                      const float* __restrict__ hd2,
                      const float* __restrict__ pWm, const float* __restrict__ pbm,
                      const int* __restrict__ dataPtr)
{
    int t = threadIdx.x;  // 128
    if (blockIdx.x >= 53) {
        int b = blockIdx.x - 53;
        if (t < 32) {
            const int* d = dataPtr + b * NN;
            int cnt = 0;
            for (int base = 0; base < NN; base += 32) {
                int v = d[base + t];
                unsigned m = __ballot_sync(0xffffffffu, v != 0);
                if (v != 0) g_idx[b][cnt + __popc(m & ((1u << t) - 1u))] = base + t;
                cnt += __popc(m);
            }
            if (t == 0) g_n[b] = cnt;
        }
        return;
    }
    if (blockIdx.x == 48) {
        __shared__ float sh[128];
        __shared__ float sh2[4];
        const float* e = Aext + (size_t)NN * FF;
        float acc = 0.f;
        #pragma unroll 8
        for (int k = 0; k < FF; k++) acc += e[k] * hW[k * FF + t];
        g_hlast[t] = acc;
        sh[t] = acc * hs2[t];
        __syncthreads();
        for (int s = 64; s > 0; s >>= 1) { if (t < s) sh[t] += sh[t + s]; __syncthreads(); }
        if (t == 0) g_sL[0] = sh[0];
        __syncthreads();
        sh[t] = acc * hd2[t];
        __syncthreads();
        for (int s = 64; s > 0; s >>= 1) { if (t < s) sh[t] += sh[t + s]; __syncthreads(); }
        if (t == 0) g_sL[1] = sh[0];
        float bc = 0.f;
        #pragma unroll 8
        for (int m = 0; m < FF; m++) bc += pbm[m] * hW[m * FF + t];
        g_bcomb[t] = bc;
        __syncthreads();
        float v = 0.f;
        #pragma unroll 8
        for (int c = 0; c < FF; c++) v += hW[t * FF + c] * hd2[c];
        sh[t] = v;
        __syncthreads();
        float cbp = pbm[t] * sh[t];
        #pragma unroll
        for (int o = 16; o > 0; o >>= 1) cbp += __shfl_xor_sync(0xffffffffu, cbp, o);
        if ((t & 31) == 0) sh2[t >> 5] = cbp;
        float uu = 0.f;
        #pragma unroll 8
        for (int m = 0; m < FF; m++) uu += pWm[(size_t)t * 2 * FF + m] * sh[m];
        g_udst[t] = uu;
        __syncthreads();
        if (t == 0) g_cdst = sh2[0] + sh2[1] + sh2[2] + sh2[3];
        return;
    }

    bool wcomb = (blockIdx.x >= 49);
    int n = wcomb ? FF : NN;
    int i0 = wcomb ? (blockIdx.x - 49) * 32 : blockIdx.x * 32;

    const float* A   = wcomb ? pWm : Aext;
    int lda          = wcomb ? 2 * FF : FF;
    const float* Wp  = wcomb ? hW : W;
    float* C         = wcomb ? g_Wcomb : g_h0;

    __shared__ float shA[16][36];
    __shared__ __align__(16) float shW[16][128];

    int ty = t >> 4, tx = t & 15;
    int rowA = t >> 2, c4A = t & 3;
    const float* Arow = A + (size_t)(i0 + rowA) * lda + c4A * 4;
    float acc[4][8] = {};
    float4 pA, pW4[4];

    pA = *(const float4*)(Arow);
    #pragma unroll
    for (int p = 0; p < 4; p++) {
        int u = t + 128 * p;
        pW4[p] = *(const float4*)&Wp[(size_t)(u >> 5) * FF + (u & 31) * 4];
    }

    for (int k0 = 0; k0 < FF; k0 += 16) {
        __syncthreads();
        shA[c4A * 4 + 0][rowA] = pA.x;
        shA[c4A * 4 + 1][rowA] = pA.y;
        shA[c4A * 4 + 2][rowA] = pA.z;
        shA[c4A * 4 + 3][rowA] = pA.w;
        #pragma unroll
        for (int p = 0; p < 4; p++) {
            int u = t + 128 * p;
            *(float4*)&shW[u >> 5][(u & 31) * 4] = pW4[p];
        }
        __syncthreads();

        if (k0 + 16 < FF) {
            pA = *(const float4*)(Arow + k0 + 16);
            #pragma unroll
            for (int p = 0; p < 4; p++) {
                int u = t + 128 * p;
                pW4[p] = *(const float4*)&Wp[(size_t)(k0 + 16 + (u >> 5)) * FF + (u & 31) * 4];
            }
        }

        #pragma unroll
        for (int k = 0; k < 16; k++) {
            float av[4], bv[8];
            *(float4*)&av[0] = *(float4*)&shA[k][ty * 4];
            *(float4*)&bv[0] = *(float4*)&shW[k][tx * 8];
            *(float4*)&bv[4] = *(float4*)&shW[k][tx * 8 + 4];
            #pragma unroll
            for (int r = 0; r < 4; r++)
                #pragma unroll
                for (int c = 0; c < 8; c++)
                    acc[r][c] = fmaf(av[r], bv[c], acc[r][c]);
        }
    }

    if (wcomb) {
        #pragma unroll
        for (int r = 0; r < 4; r++) {
            int i = i0 + ty * 4 + r;
            *(float4*)&C[(size_t)i * FF + tx * 8]     = make_float4(acc[r][0], acc[r][1], acc[r][2], acc[r][3]);
            *(float4*)&C[(size_t)i * FF + tx * 8 + 4] = make_float4(acc[r][4], acc[r][5], acc[r][6], acc[r][7]);
        }
        return;
    }

    float as8[8], ad8[8];
    #pragma unroll
    for (int c = 0; c < 8; c++) { as8[c] = asrc[tx * 8 + c]; ad8[c] = adst[tx * 8 + c]; }
    float ss[4], sd[4];
    #pragma unroll
    for (int r = 0; r < 4; r++) {
        int i = i0 + ty * 4 + r;
        float s1 = 0.f, s2 = 0.f;
        #pragma unroll
        for (int c = 0; c < 8; c++) { s1 += acc[r][c] * as8[c]; s2 += acc[r][c] * ad8[c]; }
        ss[r] = s1; sd[r] = s2;
        *(float4*)&C[(size_t)i * FF + tx * 8]     = make_float4(acc[r][0], acc[r][1], acc[r][2], acc[r][3]);
        *(float4*)&C[(size_t)i * FF + tx * 8 + 4] = make_float4(acc[r][4], acc[r][5], acc[r][6], acc[r][7]);
    }
    #pragma unroll
    for (int r = 0; r < 4; r++) {
        #pragma unroll
        for (int o = 8; o > 0; o >>= 1) {
            ss[r] += __shfl_xor_sync(0xffffffffu, ss[r], o);
            sd[r] += __shfl_xor_sync(0xffffffffu, sd[r], o);
        }
    }
    if (tx == 0) {
        #pragma unroll
        for (int r = 0; r < 4; r++) {
            int i = i0 + ty * 4 + r;
            g_si0[i] = ss[r]; g_sj0[i] = sd[r];
        }
    }
}

// ============ column-split GEMM: 32x64 tile, 128 threads, 4x4/thread ============
__global__ void gemmC(int stage,
                      const float* __restrict__ encW1,
                      const float* __restrict__ eas1, const float* __restrict__ ead1,
                      const float* __restrict__ pW, const float* __restrict__ pb)
{
    int b = blockIdx.y;
    int n = g_n[b];
    int i0 = (blockIdx.x >> 1) * 32;
    if (i0 >= n) return;
    int c0 = (blockIdx.x & 1) * 64;
    int z = blockIdx.z;
    int t = threadIdx.x;  // 128

    const float* A = g_mean + (size_t)b * NN * FF;
    const float* Wp; const float* bp = nullptr; int ldw;
    float* C = nullptr;
    float* kldOut = nullptr; int kldExp = 0;
    int epi;

    if (stage == 0) {
        Wp = encW1 + c0; ldw = FF; C = g_xc + (size_t)b * NN * FF;
        epi = 1;
    } else if (z == 0) {
        Wp = pW + c0; ldw = 2 * FF; bp = pb + c0;
        kldOut = g_kldrow1 + b * NN; kldExp = 0; epi = 2;
    } else {
        Wp = pW + FF + c0; ldw = 2 * FF; bp = pb + FF + c0;
        kldOut = g_kldrow2 + b * NN; kldExp = 1; epi = 2;
    }

    __shared__ float shA[16][36];
    __shared__ __align__(16) float shW[16][64];

    int ty = t >> 4, tx = t & 15;
    int rowA = t >> 2, c4A = t & 3;
    bool rowAok = (i0 + rowA < n);
    const float* Arow = A + (size_t)(i0 + (rowAok ? rowA : 0)) * FF + c4A * 4;
    float acc[4][4] = {};
    float4 pA, pW2[2];

    pA = rowAok ? *(const float4*)(Arow) : make_float4(0.f, 0.f, 0.f, 0.f);
    #pragma unroll
    for (int p = 0; p < 2; p++) {
        int u = t + 128 * p;
        pW2[p] = *(const float4*)&Wp[(size_t)(u >> 4) * ldw + (u & 15) * 4];
    }

    for (int k0 = 0; k0 < FF; k0 += 16) {
        __syncthreads();
        shA[c4A * 4 + 0][rowA] = pA.x;
        shA[c4A * 4 + 1][rowA] = pA.y;
        shA[c4A * 4 + 2][rowA] = pA.z;
        shA[c4A * 4 + 3][rowA] = pA.w;
        #pragma unroll
        for (int p = 0; p < 2; p++) {
            int u = t + 128 * p;
            *(float4*)&shW[u >> 4][(u & 15) * 4] = pW2[p];
        }
        __syncthreads();

        if (k0 + 16 < FF) {
            pA = rowAok ? *(const float4*)(Arow + k0 + 16) : make_float4(0.f, 0.f, 0.f, 0.f);
            #pragma unroll
            for (int p = 0; p < 2; p++) {
                int u = t + 128 * p;
                pW2[p] = *(const float4*)&Wp[(size_t)(k0 + 16 + (u >> 4)) * ldw + (u & 15) * 4];
            }
        }

        #pragma unroll
        for (int k = 0; k < 16; k++) {
            float av[4], bv[4];
            *(float4*)&av[0] = *(float4*)&shA[k][ty * 4];
            *(float4*)&bv[0] = *(float4*)&shW[k][tx * 4];
            #pragma unroll
            for (int r = 0; r < 4; r++)
                #pragma unroll
                for (int c = 0; c < 4; c++)
                    acc[r][c] = fmaf(av[r], bv[c], acc[r][c]);
        }
    }

    if (epi == 2) {
        float bv4[4];
        #pragma unroll
        for (int c = 0; c < 4; c++) bv4[c] = bp[tx * 4 + c];
        #pragma unroll
        for (int r = 0; r < 4; r++) {
            int i = i0 + ty * 4 + r;
            float kp = 0.f;
            #pragma unroll
            for (int c = 0; c < 4; c++) {
                float v = acc[r][c] + bv4[c];
                kp += (kldExp == 0) ? v * v : (expm1f(v) - v);
            }
            #pragma unroll
            for (int o = 8; o > 0; o >>= 1) kp += __shfl_xor_sync(0xffffffffu, kp, o);
            if (tx == 0 && i < n) atomicAdd(&kldOut[i], kp);
        }
        return;
    }

    float as4[4], ad4[4];
    #pragma unroll
    for (int c = 0; c < 4; c++) {
        int idx = c0 + tx * 4 + c;
        as4[c] = eas1[idx]; ad4[c] = ead1[idx];
    }
    float ss[4], sd[4];
    #pragma unroll
    for (int r = 0; r < 4; r++) {
        int i = i0 + ty * 4 + r;
        float s1 = 0.f, s2 = 0.f;
        #pragma unroll
        for (int c = 0; c < 4; c++) {
            float v = acc[r][c];
            s1 += v * as4[c]; s2 += v * ad4[c];
        }
        ss[r] = s1; sd[r] = s2;
        if (i < n)
            *(float4*)&C[(size_t)i * FF + c0 + tx * 4] = make_float4(acc[r][0], acc[r][1], acc[r][2], acc[r][3]);
    }
    #pragma unroll
    for (int r = 0; r < 4; r++) {
        #pragma unroll
        for (int o = 8; o > 0; o >>= 1) {
            ss[r] += __shfl_xor_sync(0xffffffffu, ss[r], o);
            sd[r] += __shfl_xor_sync(0xffffffffu, sd[r], o);
        }
    }
    if (tx == 0) {
        #pragma unroll
        for (int r = 0; r < 4; r++) {
            int i = i0 + ty * 4 + r;
            if (i < n) { atomicAdd(&g_sic[b * NN + i], ss[r]); atomicAdd(&g_sjc[b * NN + i], sd[r]); }
        }
    }
}

// ============ attention prep ============
#define SQ_SJV  0
#define SQ_QV   (SQ_SJV + 1536)
#define SQ_RNK  (SQ_QV + 1536)
#define SQ_ORD  (SQ_RNK + 1536)
#define SQ_CNT  (SQ_ORD + 1536)
#define SQ_TOT  (SQ_CNT + NCHK * NB)
#define SQ_BST  (SQ_TOT + 128)
#define SQ_SJO  (SQ_BST + 132)
#define SQ_VSO  (SQ_SJO + 1536)
#define SQ_BSO  (SQ_VSO + 1536)
#define SQ_SV   (SQ_BSO + 1536)
#define SQ_SB   (SQ_SV + NB * 128)
#define SQ_SVS  (SQ_SB + NB * 128)
#define SQ_SBS  (SQ_SVS + 132)
#define SQ_RED  (SQ_SBS + 132)
#define SQ_TOTF (SQ_RED + 80)

__global__ void attn_prep(int hId)
{
    extern __shared__ float sm[];
    float* sjv = sm + SQ_SJV;
    int*   qv  = (int*)(sm + SQ_QV);
    int*   rnk = (int*)(sm + SQ_RNK);
    int*   ord = (int*)(sm + SQ_ORD);
    int*   cnt = (int*)(sm + SQ_CNT);
    int*   tot = (int*)(sm + SQ_TOT);
    int*   bst = (int*)(sm + SQ_BST);
    float* sjo = sm + SQ_SJO;
    float* vso = sm + SQ_VSO;
    float* bso = sm + SQ_BSO;
    float* Sv  = sm + SQ_SV;
    float* Sb  = sm + SQ_SB;
    float* SvS = sm + SQ_SVS;
    float* SbS = sm + SQ_SBS;
    float* red = sm + SQ_RED;

    int b = blockIdx.x;
    int n = g_n[b];
    int t = threadIdx.x;  // 1024
    int lane = t & 31, warp = t >> 5;
    const float* Hb = hId ? (g_xc + (size_t)b * NN * FF) : g_h0;

    // score load (L1: via idx indirection, no gather copy)
    if (hId == 0) {
        for (int jj = t; jj < n; jj += 1024)
            sjv[jj] = g_sj0[g_idx[b][jj]];
    } else {
        for (int u = t; u < n; u += 1024) sjv[u] = g_sjc[b * NN + u];
    }
    for (int u = t; u < NCHK * NB; u += 1024) cnt[u] = 0;
    __syncthreads();

    float mn = 1e30f, mx = -1e30f;
    for (int u = t; u < n; u += 1024) {
        float s = sjv[u];
        mn = fminf(mn, s); mx = fmaxf(mx, s);
    }
    #pragma unroll
    for (int o = 16; o > 0; o >>= 1) {
        mn = fminf(mn, __shfl_xor_sync(0xffffffffu, mn, o));
        mx = fmaxf(mx, __shfl_xor_sync(0xffffffffu, mx, o));
    }
    if (lane == 0) { red[warp] = mn; red[32 + warp] = mx; }
    __syncthreads();
    if (t == 0) {
        float a = 1e30f, z = -1e30f;
        for (int w = 0; w < 32; w++) { a = fminf(a, red[w]); z = fmaxf(z, red[32 + w]); }
        float span = z - a;
        float sc = (span > 1e-20f) ? (float)NB / span : 0.f;
        red[64] = z; red[65] = sc;
        g_bmax[b] = z; g_bscale[b] = sc;
    }
    __syncthreads();
    float bmax = red[64], bscale = red[65];

    int nchk = (n + 31) >> 5;
    for (int ch = warp; ch < nchk; ch += 32) {
        int j = ch * 32 + lane;
        int q = -1;
        if (j < n) {
            q = (int)((bmax - sjv[j]) * bscale);
            q = max(0, min(NB - 1, q));
        }
        unsigned mask = __match_any_sync(0xffffffffu, q);
        int rank = __popc(mask & ((1u << lane) - 1u));
        if (j < n) {
            qv[j] = q; rnk[j] = rank;
            if (rank == 0) cnt[ch * NB + q] = __popc(mask);
        }
    }
    __syncthreads();

    if (t < NB) {
        int run = 0;
        for (int ch = 0; ch < nchk; ch++) {
            int c = cnt[ch * NB + t];
            cnt[ch * NB + t] = run;
            run += c;
        }
        tot[t] = run;
    }
    __syncthreads();
    if (t < 32) {
        int base = t * 4;
        int h0 = tot[base], h1 = tot[base + 1], h2 = tot[base + 2], h3 = tot[base + 3];
        int s = h0 + h1 + h2 + h3, inc = s;
        #pragma unroll
        for (int o = 1; o < 32; o <<= 1) {
            int v = __shfl_up_sync(0xffffffffu, inc, o);
            if (lane >= o) inc += v;
        }
        int ex = inc - s;
        bst[base] = ex; bst[base + 1] = ex + h0;
        bst[base + 2] = ex + h0 + h1; bst[base + 3] = ex + h0 + h1 + h2;
        if (t == 31) bst[NB] = inc;
    }
    __syncthreads();
    if (t <= NB) g_bstart[b][t] = bst[t];

    for (int j = t; j < n; j += 1024) {
        int q = qv[j];
        int pos = bst[q] + cnt[(j >> 5) * NB + q] + rnk[j];
        ord[pos] = j;
    }
    __syncthreads();

    // per-position arrays; compose indirection: ord becomes H-row index
    for (int pos = t; pos < n; pos += 1024) {
        int j = ord[pos];
        float s = sjv[j];
        float v = __expf(s), w = __expf(0.2f * s);
        sjo[pos] = s; vso[pos] = v; bso[pos] = w;
        int jx = hId ? j : g_idx[b][j];
        ord[pos] = jx;
        g_ord[b][pos] = jx; g_sjo[b][pos] = s; g_vso[b][pos] = v; g_bso[b][pos] = w;
    }
    __syncthreads();

    // per-bucket vector + scalar sums: one warp per bucket, float4 channels, 2-stage prefetch
    for (int q = warp; q < NB; q += 32) {
        int p0 = bst[q], p1 = bst[q + 1];
        float4 av = make_float4(0.f, 0.f, 0.f, 0.f);
        float4 ab = make_float4(0.f, 0.f, 0.f, 0.f);
        float svs = 0.f, sbs = 0.f;
        float4 hv_n = make_float4(0.f, 0.f, 0.f, 0.f);
        if (p0 < p1) hv_n = *(const float4*)&Hb[(size_t)ord[p0] * FF + lane * 4];
        for (int p = p0; p < p1; p++) {
            float4 hv = hv_n;
            if (p + 1 < p1) hv_n = *(const float4*)&Hb[(size_t)ord[p + 1] * FF + lane * 4];
            float wv = vso[p], wb = bso[p];
            av.x = fmaf(wv, hv.x, av.x); av.y = fmaf(wv, hv.y, av.y);
            av.z = fmaf(wv, hv.z, av.z); av.w = fmaf(wv, hv.w, av.w);
            ab.x = fmaf(wb, hv.x, ab.x); ab.y = fmaf(wb, hv.y, ab.y);
            ab.z = fmaf(wb, hv.z, ab.z); ab.w = fmaf(wb, hv.w, ab.w);
            svs += wv; sbs += wb;
        }
        *(float4*)&Sv[q * 128 + lane * 4] = av;
        *(float4*)&Sb[q * 128 + lane * 4] = ab;
        if (lane == 0) { SvS[q] = svs; SbS[q] = sbs; }
    }
    __syncthreads();

    if (t < 128) {
        float run = 0.f;
        for (int q = 0; q < NB; q++) { g_Cv[b][q * 128 + t] = run; run += Sv[q * 128 + t]; }
        g_Cv[b][NB * 128 + t] = run;
    } else if (t < 256) {
        int c = t - 128;
        float run = 0.f;
        for (int q = 0; q < NB; q++) { g_Cb[b][q * 128 + c] = run; run += Sb[q * 128 + c]; }
        g_Cb[b][NB * 128 + c] = run;
    } else if (t == 256) {
        float run = 0.f;
        for (int q = 0; q < NB; q++) { g_CvS[b][q] = run; run += SvS[q]; }
        g_CvS[b][NB] = run;
    } else if (t == 257) {
        float run = 0.f;
        for (int q = 0; q < NB; q++) { g_CbS[b][q] = run; run += SbS[q]; }
        g_CbS[b][NB] = run;
    }
}

// ============ per-row combine (branchless walk, 2-stage prefetch) ============
__device__ __forceinline__ float4 combine_row(int b, int i, int lane,
                                              const float* __restrict__ H, float si)
{
    float uu = __expf(si), aa = __expf(0.2f * si);
    float th = -si;
    int qt = (int)((g_bmax[b] - th) * g_bscale[b]);
    qt = max(0, min(NB - 1, qt));
    int p0 = g_bstart[b][qt], p1 = g_bstart[b][qt + 1];

    float4 pv = *(const float4*)&g_Cv[b][qt * 128 + lane * 4];
    float4 pb = *(const float4*)&g_Cb[b][qt * 128 + lane * 4];
    float pvs = g_CvS[b][qt], pbs = g_CbS[b][qt];

    float4 hv_n = make_float4(0.f, 0.f, 0.f, 0.f);
    if (p0 < p1) hv_n = *(const float4*)&H[(size_t)g_ord[b][p0] * FF + lane * 4];
    for (int p = p0; p < p1; p++) {
        float4 hv = hv_n;
        if (p + 1 < p1) hv_n = *(const float4*)&H[(size_t)g_ord[b][p + 1] * FF + lane * 4];
        bool in = (g_sjo[b][p] >= th);
        float w  = in ? g_vso[b][p] : 0.f;
        float wb = in ? g_bso[b][p] : 0.f;
        pv.x = fmaf(w, hv.x, pv.x); pv.y = fmaf(w, hv.y, pv.y);
        pv.z = fmaf(w, hv.z, pv.z); pv.w = fmaf(w, hv.w, pv.w);
        pb.x = fmaf(wb, hv.x, pb.x); pb.y = fmaf(wb, hv.y, pb.y);
        pb.z = fmaf(wb, hv.z, pb.z); pb.w = fmaf(wb, hv.w, pb.w);
        pvs += w; pbs += wb;
    }

    float totbs = g_CbS[b][NB];
    float4 tb = *(const float4*)&g_Cb[b][NB * 128 + lane * 4];
    float inv = 1.f / (uu * pvs + aa * (totbs - pbs));
    float4 o;
    o.x = (uu * pv.x + aa * (tb.x - pb.x)) * inv;
    o.y = (uu * pv.y + aa * (tb.y - pb.y)) * inv;
    o.z = (uu * pv.z + aa * (tb.z - pb.z)) * inv;
    o.w = (uu * pv.w + aa * (tb.w - pb.w)) * inv;
    o.x = (o.x > 0.f) ? o.x : expm1f(o.x);
    o.y = (o.y > 0.f) ? o.y : expm1f(o.y);
    o.z = (o.z > 0.f) ? o.z : expm1f(o.z);
    o.w = (o.w > 0.f) ? o.w : expm1f(o.w);
    return o;
}

// ============ combine -> g_mean; zeroes accumulators for the next stage's atomics ============
__global__ void attn_combine(int hId)
{
    int b = blockIdx.y;
    int n = g_n[b];
    int warp = threadIdx.x >> 5, lane = threadIdx.x & 31;
    int i = blockIdx.x * 8 + warp;
    if (i >= n) return;
    const float* H = hId ? (g_xc + (size_t)b * NN * FF) : g_h0;
    float si = hId ? g_sic[b * NN + i] : g_si0[g_idx[b][i]];
    float4 o = combine_row(b, i, lane, H, si);
    *(float4*)&g_mean[(size_t)b * NN * FF + (size_t)i * FF + lane * 4] = o;
    if (lane == 0) {
        if (hId == 0) { g_sic[b * NN + i] = 0.f; g_sjc[b * NN + i] = 0.f; }
        else          { g_kldrow1[b * NN + i] = 0.f; g_kldrow2[b * NN + i] = 0.f; }
    }
}

// ============ decoder: algebraic single-row attention over g_mean (x2) ============
__global__ void dec2_kernel()
{
    int b = blockIdx.x;
    int n = g_n[b];
    const float* M = g_mean + (size_t)b * NN * FF;
    int t = threadIdx.x;            // 1024
    int warp = t >> 5, lane = t & 31;
    __shared__ float smb[32 * 128];
    __shared__ float sS[32];
    __shared__ float sTot;

    float4 u4 = *(const float4*)&g_udst[lane * 4];
    float cb = g_cdst;
    float sLs = g_sL[0];

    float4 mb = make_float4(0.f, 0.f, 0.f, 0.f);
    float S = 0.f;
    for (int i = warp; i < n; i += 32) {
        float4 m = *(const float4*)&M[(size_t)i * FF + lane * 4];
        float d = m.x * u4.x + m.y * u4.y + m.z * u4.z + m.w * u4.w;
        #pragma unroll
        for (int o = 16; o > 0; o >>= 1) d += __shfl_xor_sync(0xffffffffu, d, o);
        float e = sLs + d + cb;
        e = (e >= 0.f) ? e : 0.2f * e;
        float w = __expf(e);
        S += w;
        mb.x = fmaf(w, m.x, mb.x); mb.y = fmaf(w, m.y, mb.y);
        mb.z = fmaf(w, m.z, mb.z); mb.w = fmaf(w, m.w, mb.w);
    }
    *(float4*)&smb[warp * 128 + lane * 4] = mb;
    if (lane == 0) sS[warp] = S;
    __syncthreads();
    float colsum = 0.f;
    if (t < 128) {
        #pragma unroll
        for (int w = 0; w < 32; w++) colsum += smb[w * 128 + t];
    }
    if (t == 128) {
        float s = 0.f;
        for (int w = 0; w < 32; w++) s += sS[w];
        sTot = s;
    }
    __syncthreads();
    if (t < 128) smb[t] = colsum;
    __syncthreads();
    if (t < 128) {
        float acc = 0.f;
        #pragma unroll 8
        for (int k = 0; k < FF; k++) acc += smb[k] * g_Wcomb[k * FF + t];
        float eL = sLs + g_sL[1];
        eL = (eL >= 0.f) ? eL : 0.2f * eL;
        float wL = __expf(eL);
        float Stot = sTot;
        float val = (acc + Stot * g_bcomb[t] + wL * g_hlast[t]) / (Stot + wL);
        g_feat[b * FF + t] = fmaxf(val, 0.f);
    }
}

// ============ output MLP + KLD total ============
__global__ void final_kernel(const float* __restrict__ W1, const float* __restrict__ b1,
                             const float* __restrict__ W2, const float* __restrict__ b2,
                             float* __restrict__ out)
{
    int t = threadIdx.x; // 256
    __shared__ float shh[16 * 128];
    for (int u = t; u < 16 * 128; u += 256) {
        int b = u >> 7, c = u & 127;
        const float* f = g_feat + b * FF;
        float acc = b1[c];
        for (int k = 0; k < FF; k++) acc += f[k] * W1[k * FF + c];
        shh[u] = fmaxf(acc, 0.f);
    }
    __shared__ float shr[256];
    float kld = 0.f;
    for (int b = 0; b < BB; b++) {
        int n = g_n[b];
        float p = 0.f;
        for (int r = t; r < n; r += 256) p += g_kldrow1[b * NN + r] + g_kldrow2[b * NN + r];
        shr[t] = p;
        __syncthreads();
        for (int s = 128; s > 0; s >>= 1) { if (t < s) shr[t] += shr[t + s]; __syncthreads(); }
        if (t == 0) kld += 0.5f * shr[0] / fmaxf((float)n, 1.f);
        __syncthreads();
    }
    __syncthreads();
    if (t < 16) {
        float acc = b2[0];
        for (int c = 0; c < FF; c++) acc += shh[t * FF + c] * W2[c];
        out[t] = acc;
    }
    if (t == 0) out[16] = kld;
}

// ============ launch ============
extern "C" void kernel_launch(void* const* d_in, const int* in_sizes, int n_in,
                              void* d_out, int out_size)
{
    (void)in_sizes; (void)n_in; (void)out_size;
    const int*   data  = (const int*)d_in[0];
    const float* embed = (const float*)d_in[1];
    const float* encW  = (const float*)d_in[2];
    const float* eas   = (const float*)d_in[3];
    const float* ead   = (const float*)d_in[4];
    const float* pW    = (const float*)d_in[5];
    const float* pb    = (const float*)d_in[6];
    const float* dW    = (const float*)d_in[7];
    const float* das   = (const float*)d_in[8];
    const float* dad   = (const float*)d_in[9];
    const float* oW1   = (const float*)d_in[10];
    const float* ob1   = (const float*)d_in[11];
    const float* oW2   = (const float*)d_in[12];
    const float* ob2   = (const float*)d_in[13];
    float* out = (float*)d_out;

    const int SMEMB = SQ_TOTF * 4;
    cudaFuncSetAttribute(attn_prep, cudaFuncAttributeMaxDynamicSharedMemorySize, SMEMB);

    // 1) layer-0 h + si0/sj0 (+ hlast/bcomb/u/cb blk48, Wcomb 49-52, compaction 53-68)
    gemm0<<<dim3(69, 1), 128>>>(embed, encW, eas, ead, dW, das, dad, pW, pb, data);
    // 2) L1 attention prep (no gather; idx composed into bucket order)
    attn_prep<<<16, 1024, SMEMB>>>(0);
    // 3) L1 combine -> g_mean (zeroes sic/sjc for stage-4 atomics)
    attn_combine<<<dim3(192, 16), 256>>>(0);
    // 4) L1 linear (col-split): x1 @ encW1 -> g_xc + atomic sic/sjc
    gemmC<<<dim3(96, 16), 128>>>(0, encW + FF * FF, eas + FF, ead + FF, pW, pb);
    // 5) L2 attention prep
    attn_prep<<<16, 1024, SMEMB>>>(1);
    // 6) L2 combine -> g_mean (zeroes kldrows for stage-7 atomics)
    attn_combine<<<dim3(192, 16), 256>>>(1);
    // 7) param head KLD only (z=0 mean, z=1 sigma), col-split
    gemmC<<<dim3(96, 16, 2), 128>>>(1, encW + FF * FF, eas + FF, ead + FF, pW, pb);
    // 8) decoder row (algebraic)
    dec2_kernel<<<16, 1024>>>();
    // 9) output MLP + KLD
    final_kernel<<<1, 256>>>(oW1, ob1, oW2, ob2, out);
}